// round 2
// baseline (speedup 1.0000x reference)
#include <cuda_runtime.h>
#include <stdint.h>

#define NVOX 200000
#define KOFF 27
#define PPK  400000
#define CIN  32
#define CMID 64
#define COUT 32

typedef unsigned long long ull;

// ---------------- scratch (static __device__ arrays; no allocs) ----------------
__device__ __align__(16) float g_h[(size_t)NVOX * CMID];        // 51.2 MB hidden layer
__device__ __align__(16) int2  g_pairs[(size_t)KOFF * PPK];     // compacted (in,out) per offset
__device__ int g_cnt[KOFF];
__device__ int g_is64;

// ---------------- packed f32x2 helpers (sm_100+) ----------------
__device__ __forceinline__ ull pack2(float x) {
    ull r; asm("mov.b64 %0, {%1, %1};" : "=l"(r) : "f"(x)); return r;
}
__device__ __forceinline__ void fma2(ull& acc, ull a, ull b) {
    asm("fma.rn.f32x2 %0, %1, %2, %0;" : "+l"(acc) : "l"(a), "l"(b));
}
__device__ __forceinline__ void unpack2(ull v, float& lo, float& hi) {
    asm("mov.b64 {%0, %1}, %2;" : "=f"(lo), "=f"(hi) : "l"(v));
}

// ---------------- dtype detect + counter reset ----------------
// Reference requests int64 indices, but default-config JAX silently emits
// int32. Detect at runtime: true int64 (values < 2^31, non-negative) has all
// odd 32-bit words == 0; 64 consecutive zero odd-words from random int32
// indices in [0, 200000) has ~0 probability.
__global__ void detect_kernel(const unsigned* __restrict__ idx_words) {
    int t = threadIdx.x;
    if (t < KOFF) g_cnt[t] = 0;
    if (t == 63) {
        int is64 = 1;
        #pragma unroll 1
        for (int i = 0; i < 64; i++)
            if (idx_words[2 * i + 1] != 0u) { is64 = 0; break; }
        g_is64 = is64;
    }
}

// ---------------- zero h and out ----------------
__global__ void zero_kernel(float4* __restrict__ out4, int out_n4) {
    size_t i      = (size_t)blockIdx.x * blockDim.x + threadIdx.x;
    size_t stride = (size_t)gridDim.x * blockDim.x;
    float4 z = make_float4(0.f, 0.f, 0.f, 0.f);
    float4* h4 = (float4*)g_h;
    const size_t nh4 = (size_t)NVOX * CMID / 4;
    for (size_t j = i; j < nh4; j += stride) h4[j] = z;
    for (size_t j = i; j < (size_t)out_n4; j += stride) out4[j] = z;
}

// ---------------- compaction: keep only valid pairs (mask > 0.5) ----------------
__global__ void compact_kernel(const void* __restrict__ in_idx,
                               const void* __restrict__ out_idx,
                               const float* __restrict__ mask) {
    int k = blockIdx.y;
    int p = blockIdx.x * blockDim.x + threadIdx.x;
    int is64 = g_is64;

    bool valid = false;
    int vi = 0, vo = 0;
    if (p < PPK) {
        size_t g = (size_t)k * PPK + p;
        valid = mask[g] > 0.5f;
        if (valid) {
            if (is64) {
                vi = (int)((const long long*)in_idx)[g];
                vo = (int)((const long long*)out_idx)[g];
            } else {
                vi = ((const int*)in_idx)[g];
                vo = ((const int*)out_idx)[g];
            }
        }
    }
    unsigned b = __ballot_sync(0xffffffffu, valid);
    int lane = threadIdx.x & 31;
    int cntw = __popc(b);
    int pref = __popc(b & ((1u << lane) - 1u));
    int base = 0;
    if (lane == 0 && cntw) base = atomicAdd(&g_cnt[k], cntw);
    base = __shfl_sync(0xffffffffu, base, 0);
    if (valid)
        g_pairs[(size_t)k * PPK + base + pref] = make_int2(vi, vo);
}

// ---------------- vectorized global reduction (sm_90+) ----------------
__device__ __forceinline__ void red_add_v4(float* p, float a, float b, float c, float d) {
    asm volatile("red.relaxed.gpu.global.add.v4.f32 [%0], {%1,%2,%3,%4};"
                 :: "l"(p), "f"(a), "f"(b), "f"(c), "f"(d) : "memory");
}

// ---------------- layer 1: feats[in] @ W_in[k] -> atomic into g_h[out] ----------------
__global__ void __launch_bounds__(128)
conv1_kernel(const float* __restrict__ feats, const float* __restrict__ W) {
    __shared__ __align__(16) float Ws[CIN * CMID];   // 8 KB
    int k = blockIdx.y;
    {
        const float4* Wk = (const float4*)(W + (size_t)k * CIN * CMID);
        for (int i = threadIdx.x; i < CIN * CMID / 4; i += blockDim.x)
            ((float4*)Ws)[i] = Wk[i];
    }
    __syncthreads();

    int cnt = g_cnt[k];
    const int2* pk = g_pairs + (size_t)k * PPK;

    for (int i = blockIdx.x * blockDim.x + threadIdx.x; i < cnt;
         i += gridDim.x * blockDim.x) {
        int2 pr = pk[i];
        const float4* xr = (const float4*)(feats + (size_t)pr.x * CIN);

        ull y2[CMID / 2];
        #pragma unroll
        for (int d = 0; d < CMID / 2; d++) y2[d] = 0ull;

        #pragma unroll 1
        for (int c4 = 0; c4 < CIN / 4; c4++) {
            float4 xc = __ldg(xr + c4);
            ull xa = pack2(xc.x), xb = pack2(xc.y);
            ull xcp = pack2(xc.z), xd = pack2(xc.w);
            const ull* w0 = (const ull*)(Ws + (c4 * 4) * CMID);  // row stride = 32 ull
            #pragma unroll
            for (int d = 0; d < CMID / 2; d++) {
                fma2(y2[d], xa,  w0[d]);
                fma2(y2[d], xb,  w0[CMID / 2 + d]);
                fma2(y2[d], xcp, w0[CMID + d]);
                fma2(y2[d], xd,  w0[3 * CMID / 2 + d]);
            }
        }

        float* hp = g_h + (size_t)pr.y * CMID;
        #pragma unroll
        for (int d = 0; d < CMID / 2; d += 2) {
            float a, b, c, e;
            unpack2(y2[d], a, b);
            unpack2(y2[d + 1], c, e);
            red_add_v4(hp + 2 * d, a, b, c, e);
        }
    }
}

// ---------------- layer 2: relu(g_h[in]) @ W_out[k] -> atomic into out[out] ----------------
__global__ void __launch_bounds__(128)
conv2_kernel(float* __restrict__ out, const float* __restrict__ W) {
    __shared__ __align__(16) float Ws[CMID * COUT];  // 8 KB
    int k = blockIdx.y;
    {
        const float4* Wk = (const float4*)(W + (size_t)k * CMID * COUT);
        for (int i = threadIdx.x; i < CMID * COUT / 4; i += blockDim.x)
            ((float4*)Ws)[i] = Wk[i];
    }
    __syncthreads();

    int cnt = g_cnt[k];
    const int2* pk = g_pairs + (size_t)k * PPK;

    for (int i = blockIdx.x * blockDim.x + threadIdx.x; i < cnt;
         i += gridDim.x * blockDim.x) {
        int2 pr = pk[i];
        const float4* xr = (const float4*)(g_h + (size_t)pr.x * CMID);

        ull y2[COUT / 2];
        #pragma unroll
        for (int d = 0; d < COUT / 2; d++) y2[d] = 0ull;

        #pragma unroll 1
        for (int c4 = 0; c4 < CMID / 4; c4++) {
            float4 xc = __ldg(xr + c4);
            // fused ReLU on hidden activations (scalar, pre-pack)
            xc.x = fmaxf(xc.x, 0.f);
            xc.y = fmaxf(xc.y, 0.f);
            xc.z = fmaxf(xc.z, 0.f);
            xc.w = fmaxf(xc.w, 0.f);
            ull xa = pack2(xc.x), xb = pack2(xc.y);
            ull xcp = pack2(xc.z), xd = pack2(xc.w);
            const ull* w0 = (const ull*)(Ws + (c4 * 4) * COUT);  // row stride = 16 ull
            #pragma unroll
            for (int d = 0; d < COUT / 2; d++) {
                fma2(y2[d], xa,  w0[d]);
                fma2(y2[d], xb,  w0[COUT / 2 + d]);
                fma2(y2[d], xcp, w0[COUT + d]);
                fma2(y2[d], xd,  w0[3 * COUT / 2 + d]);
            }
        }

        float* op = out + (size_t)pr.y * COUT;
        #pragma unroll
        for (int d = 0; d < COUT / 2; d += 2) {
            float a, b, c, e;
            unpack2(y2[d], a, b);
            unpack2(y2[d + 1], c, e);
            red_add_v4(op + 2 * d, a, b, c, e);
        }
    }
}

// ---------------- launch ----------------
extern "C" void kernel_launch(void* const* d_in, const int* in_sizes, int n_in,
                              void* d_out, int out_size) {
    const float* feats   = (const float*)d_in[0];
    const void*  in_idx  = d_in[1];
    const void*  out_idx = d_in[2];
    const float* mask    = (const float*)d_in[3];
    const float* W_in    = (const float*)d_in[4];
    const float* W_out   = (const float*)d_in[5];
    float* out = (float*)d_out;

    detect_kernel<<<1, 64>>>((const unsigned*)in_idx);
    zero_kernel<<<4096, 256>>>((float4*)out, out_size / 4);

    dim3 cg((PPK + 255) / 256, KOFF);
    compact_kernel<<<cg, 256>>>(in_idx, out_idx, mask);

    dim3 g1(512, KOFF);
    conv1_kernel<<<g1, 128>>>(feats, W_in);
    conv2_kernel<<<g1, 128>>>(out, W_out);
}

// round 3
// speedup vs baseline: 1.4328x; 1.4328x over previous
#include <cuda_runtime.h>
#include <stdint.h>

#define NVOX 200000
#define KOFF 27
#define PPK  400000
#define CIN  32
#define CMID 64
#define COUT 32

typedef unsigned long long ull;

// ---------------- scratch (static __device__ arrays; no allocs) ----------------
__device__ __align__(16) float g_h[(size_t)NVOX * CMID];        // 51.2 MB hidden
__device__ __align__(16) int2  g_pairs[(size_t)KOFF * PPK];     // compacted (in,out)
__device__ int g_cnt[KOFF];
__device__ int g_is64;

// ---------------- packed f32x2 helpers (sm_100+) ----------------
__device__ __forceinline__ ull pack2(float x) {
    ull r; asm("mov.b64 %0, {%1, %1};" : "=l"(r) : "f"(x)); return r;
}
__device__ __forceinline__ void fma2(ull& acc, ull a, ull b) {
    asm("fma.rn.f32x2 %0, %1, %2, %0;" : "+l"(acc) : "l"(a), "l"(b));
}
__device__ __forceinline__ void unpack2(ull v, float& lo, float& hi) {
    asm("mov.b64 {%0, %1}, %2;" : "=f"(lo), "=f"(hi) : "l"(v));
}
__device__ __forceinline__ void red_add_v4(float* p, float a, float b, float c, float d) {
    asm volatile("red.relaxed.gpu.global.add.v4.f32 [%0], {%1,%2,%3,%4};"
                 :: "l"(p), "f"(a), "f"(b), "f"(c), "f"(d) : "memory");
}

// ---------------- dtype detect + counter reset ----------------
__global__ void detect_kernel(const unsigned* __restrict__ idx_words) {
    int t = threadIdx.x;
    if (t < KOFF) g_cnt[t] = 0;
    if (t == 63) {
        int is64 = 1;
        #pragma unroll 1
        for (int i = 0; i < 64; i++)
            if (idx_words[2 * i + 1] != 0u) { is64 = 0; break; }
        g_is64 = is64;
    }
}

// ---------------- zero h and out ----------------
__global__ void zero_kernel(float4* __restrict__ out4, int out_n4) {
    size_t i      = (size_t)blockIdx.x * blockDim.x + threadIdx.x;
    size_t stride = (size_t)gridDim.x * blockDim.x;
    float4 z = make_float4(0.f, 0.f, 0.f, 0.f);
    float4* h4 = (float4*)g_h;
    const size_t nh4 = (size_t)NVOX * CMID / 4;
    for (size_t j = i; j < nh4; j += stride) h4[j] = z;
    for (size_t j = i; j < (size_t)out_n4; j += stride) out4[j] = z;
}

// ---------------- compaction: keep only valid pairs (mask > 0.5) ----------------
__global__ void compact_kernel(const void* __restrict__ in_idx,
                               const void* __restrict__ out_idx,
                               const float* __restrict__ mask) {
    int k = blockIdx.y;
    int p = blockIdx.x * blockDim.x + threadIdx.x;
    int is64 = g_is64;

    bool valid = false;
    int vi = 0, vo = 0;
    if (p < PPK) {
        size_t g = (size_t)k * PPK + p;
        valid = mask[g] > 0.5f;
        if (valid) {
            if (is64) {
                vi = (int)((const long long*)in_idx)[g];
                vo = (int)((const long long*)out_idx)[g];
            } else {
                vi = ((const int*)in_idx)[g];
                vo = ((const int*)out_idx)[g];
            }
        }
    }
    unsigned b = __ballot_sync(0xffffffffu, valid);
    int lane = threadIdx.x & 31;
    int cntw = __popc(b);
    int pref = __popc(b & ((1u << lane) - 1u));
    int base = 0;
    if (lane == 0 && cntw) base = atomicAdd(&g_cnt[k], cntw);
    base = __shfl_sync(0xffffffffu, base, 0);
    if (valid)
        g_pairs[(size_t)k * PPK + base + pref] = make_int2(vi, vo);
}

// ==================== layer 1: register-tiled GEMM ====================
// Block tile: 128 pairs x 64 ch, K=32. 128 threads, thread tile 8x8.
__global__ void __launch_bounds__(128)
conv1_kernel(const float* __restrict__ feats, const float* __restrict__ W) {
    __shared__ __align__(16) float Xs[CIN][128];        // 16 KB, transposed x
    __shared__ __align__(16) ull   Wsh[CIN][CMID / 2];  // 8 KB
    __shared__ int Pys[128];

    const int k = blockIdx.y;
    const int cnt = g_cnt[k];
    const int base = blockIdx.x * 128;
    if (base >= cnt) return;
    const int tid = threadIdx.x;

    // W tile: 2048 floats -> smem (4 float4 per thread)
    {
        const float4* Wk = (const float4*)(W + (size_t)k * CIN * CMID);
        float4* Wd = (float4*)Wsh;
        #pragma unroll
        for (int i = 0; i < 4; i++)
            Wd[tid + i * 128] = Wk[tid + i * 128];
    }

    // Stage x rows transposed: thread tid owns pair (base+tid)
    {
        const int gi = base + tid;
        float4 r[8];
        int py = -1;
        if (gi < cnt) {
            int2 pr = g_pairs[(size_t)k * PPK + gi];
            py = pr.y;
            const float4* xr = (const float4*)(feats + (size_t)pr.x * CIN);
            #pragma unroll
            for (int c = 0; c < 8; c++) r[c] = __ldg(xr + c);
        } else {
            #pragma unroll
            for (int c = 0; c < 8; c++) r[c] = make_float4(0.f, 0.f, 0.f, 0.f);
        }
        Pys[tid] = py;
        #pragma unroll
        for (int c = 0; c < 8; c++) {      // k-lockstep, conflict-free columns
            Xs[4 * c + 0][tid] = r[c].x;
            Xs[4 * c + 1][tid] = r[c].y;
            Xs[4 * c + 2][tid] = r[c].z;
            Xs[4 * c + 3][tid] = r[c].w;
        }
    }
    __syncthreads();

    const int tx  = tid & 7;        // channel group: ch = tx*8
    const int ty  = tid >> 3;       // pair group:    m  = ty*8
    const int ty8 = ty * 8;
    const int tx4 = tx * 4;

    ull acc[8][4];
    #pragma unroll
    for (int i = 0; i < 8; i++)
        #pragma unroll
        for (int j = 0; j < 4; j++) acc[i][j] = 0ull;

    #pragma unroll 8
    for (int kk = 0; kk < CIN; kk++) {
        const float4 xa = *(const float4*)&Xs[kk][ty8];
        const float4 xb = *(const float4*)&Xs[kk][ty8 + 4];
        const ulonglong2 wa = *(const ulonglong2*)&Wsh[kk][tx4];
        const ulonglong2 wb = *(const ulonglong2*)&Wsh[kk][tx4 + 2];
        ull xp[8];
        xp[0] = pack2(xa.x); xp[1] = pack2(xa.y);
        xp[2] = pack2(xa.z); xp[3] = pack2(xa.w);
        xp[4] = pack2(xb.x); xp[5] = pack2(xb.y);
        xp[6] = pack2(xb.z); xp[7] = pack2(xb.w);
        #pragma unroll
        for (int i = 0; i < 8; i++) {
            fma2(acc[i][0], xp[i], wa.x);
            fma2(acc[i][1], xp[i], wa.y);
            fma2(acc[i][2], xp[i], wb.x);
            fma2(acc[i][3], xp[i], wb.y);
        }
    }

    // scatter 8 pairs x 8 channels
    #pragma unroll
    for (int i = 0; i < 8; i++) {
        int py = Pys[ty8 + i];
        if (py >= 0) {
            float* hp = g_h + (size_t)py * CMID + tx * 8;
            float a, b, c, d;
            unpack2(acc[i][0], a, b); unpack2(acc[i][1], c, d);
            red_add_v4(hp, a, b, c, d);
            unpack2(acc[i][2], a, b); unpack2(acc[i][3], c, d);
            red_add_v4(hp + 4, a, b, c, d);
        }
    }
}

// ==================== layer 2: register-tiled GEMM, K split ====================
// Block tile: 256 pairs x 32 ch, K=64 in two 32-k phases. 128 threads, tile 8x8.
__global__ void __launch_bounds__(128)
conv2_kernel(float* __restrict__ out, const float* __restrict__ W) {
    __shared__ __align__(16) float Xs[32][256];          // 32 KB (one k-half)
    __shared__ __align__(16) ull   Wsh[CMID][COUT / 2];  // 8 KB
    __shared__ int Pys[256];

    const int k = blockIdx.y;
    const int cnt = g_cnt[k];
    const int base = blockIdx.x * 256;
    if (base >= cnt) return;
    const int tid = threadIdx.x;

    // W tile: 2048 floats
    {
        const float4* Wk = (const float4*)(W + (size_t)k * CMID * COUT);
        float4* Wd = (float4*)Wsh;
        #pragma unroll
        for (int i = 0; i < 4; i++)
            Wd[tid + i * 128] = Wk[tid + i * 128];
    }

    // pair meta: thread owns pairs {tid, tid+128}
    const int2* pk = g_pairs + (size_t)k * PPK;
    int px0 = 0, px1 = 0;
    {
        int2 p0 = make_int2(0, -1), p1 = make_int2(0, -1);
        if (base + tid < cnt)       p0 = pk[base + tid];
        if (base + tid + 128 < cnt) p1 = pk[base + tid + 128];
        px0 = p0.x; px1 = p1.x;
        Pys[tid]       = (base + tid < cnt)       ? p0.y : -1;
        Pys[tid + 128] = (base + tid + 128 < cnt) ? p1.y : -1;
    }

    const int tx  = tid & 3;        // channel group: ch = tx*8
    const int ty  = tid >> 2;       // pair group:    m  = ty*8 (0..255)
    const int ty8 = ty * 8;
    const int tx4 = tx * 4;

    ull acc[8][4];
    #pragma unroll
    for (int i = 0; i < 8; i++)
        #pragma unroll
        for (int j = 0; j < 4; j++) acc[i][j] = 0ull;

    #pragma unroll 1
    for (int ph = 0; ph < 2; ph++) {
        __syncthreads();   // ph0: Pys/W ready; ph1: prior Xs reads done

        // stage k-half for 2 owned pairs, ReLU fused
        #pragma unroll
        for (int q = 0; q < 2; q++) {
            int m = tid + q * 128;
            bool v = (Pys[m] >= 0) || (base + m < cnt);
            const float4* hr =
                (const float4*)(g_h + (size_t)(q ? px1 : px0) * CMID + ph * 32);
            float4 r[8];
            if (base + m < cnt) {
                #pragma unroll
                for (int c = 0; c < 8; c++) {
                    float4 t = __ldg(hr + c);
                    t.x = fmaxf(t.x, 0.f); t.y = fmaxf(t.y, 0.f);
                    t.z = fmaxf(t.z, 0.f); t.w = fmaxf(t.w, 0.f);
                    r[c] = t;
                }
            } else {
                #pragma unroll
                for (int c = 0; c < 8; c++) r[c] = make_float4(0.f, 0.f, 0.f, 0.f);
            }
            (void)v;
            #pragma unroll
            for (int c = 0; c < 8; c++) {   // k-lockstep, conflict-free columns
                Xs[4 * c + 0][m] = r[c].x;
                Xs[4 * c + 1][m] = r[c].y;
                Xs[4 * c + 2][m] = r[c].z;
                Xs[4 * c + 3][m] = r[c].w;
            }
        }
        __syncthreads();

        const int kw = ph * 32;
        #pragma unroll 4
        for (int kk = 0; kk < 32; kk++) {
            const float4 xa = *(const float4*)&Xs[kk][ty8];
            const float4 xb = *(const float4*)&Xs[kk][ty8 + 4];
            const ulonglong2 wa = *(const ulonglong2*)&Wsh[kw + kk][tx4];
            const ulonglong2 wb = *(const ulonglong2*)&Wsh[kw + kk][tx4 + 2];
            ull xp[8];
            xp[0] = pack2(xa.x); xp[1] = pack2(xa.y);
            xp[2] = pack2(xa.z); xp[3] = pack2(xa.w);
            xp[4] = pack2(xb.x); xp[5] = pack2(xb.y);
            xp[6] = pack2(xb.z); xp[7] = pack2(xb.w);
            #pragma unroll
            for (int i = 0; i < 8; i++) {
                fma2(acc[i][0], xp[i], wa.x);
                fma2(acc[i][1], xp[i], wa.y);
                fma2(acc[i][2], xp[i], wb.x);
                fma2(acc[i][3], xp[i], wb.y);
            }
        }
    }

    // scatter 8 pairs x 8 channels
    #pragma unroll
    for (int i = 0; i < 8; i++) {
        int py = Pys[ty8 + i];
        if (py >= 0) {
            float* op = out + (size_t)py * COUT + tx * 8;
            float a, b, c, d;
            unpack2(acc[i][0], a, b); unpack2(acc[i][1], c, d);
            red_add_v4(op, a, b, c, d);
            unpack2(acc[i][2], a, b); unpack2(acc[i][3], c, d);
            red_add_v4(op + 4, a, b, c, d);
        }
    }
}

// ---------------- launch ----------------
extern "C" void kernel_launch(void* const* d_in, const int* in_sizes, int n_in,
                              void* d_out, int out_size) {
    const float* feats   = (const float*)d_in[0];
    const void*  in_idx  = d_in[1];
    const void*  out_idx = d_in[2];
    const float* mask    = (const float*)d_in[3];
    const float* W_in    = (const float*)d_in[4];
    const float* W_out   = (const float*)d_in[5];
    float* out = (float*)d_out;

    detect_kernel<<<1, 64>>>((const unsigned*)in_idx);
    zero_kernel<<<4096, 256>>>((float4*)out, out_size / 4);

    dim3 cg((PPK + 255) / 256, KOFF);
    compact_kernel<<<cg, 256>>>(in_idx, out_idx, mask);

    dim3 g1((PPK + 127) / 128, KOFF);
    conv1_kernel<<<g1, 128>>>(feats, W_in);
    dim3 g2((PPK + 255) / 256, KOFF);
    conv2_kernel<<<g2, 128>>>(out, W_out);
}

// round 6
// speedup vs baseline: 1.4683x; 1.0248x over previous
#include <cuda_runtime.h>
#include <stdint.h>

#define NVOX 200000
#define KOFF 27
#define PPK  400000
#define CIN  32
#define CMID 64
#define COUT 32
#define NK   (KOFF * NVOX)            /* 5,400,000 (k,n) slot space */
#define MAXPAIR (KOFF * PPK)          /* 10.8M worst-case valid pairs */

#define SCAN_BLK 2048
#define NB_USED ((NK + SCAN_BLK - 1) / SCAN_BLK)     /* 2637 */
#define NB_HIST ((NVOX + SCAN_BLK - 1) / SCAN_BLK)   /* 98   */

typedef unsigned long long ull;

// ---------------- static scratch (no runtime allocs; < 2GB total for linker) ----
// g_T serves as T1 (NK x CMID, layer-1 contributions) then is REUSED as
// T2 (NK x COUT, layer-2 contributions). Sequential dataflow makes this safe:
// gemm1->T, route1 reads T (then dead), gemm2 overwrites T, route2 reads T.
__device__ __align__(16) float g_T [(size_t)NK * CMID];       // 1.38 GB
__device__ __align__(16) float g_h [(size_t)NVOX * CMID];     // 51 MB
__device__ __align__(16) int2  g_pairs[(size_t)MAXPAIR];      // 86 MB
__device__ int  g_cnt[KOFF];
__device__ int  g_is64;
__device__ unsigned char g_used[NK];                          // 5.4 MB
__device__ int  g_uslot[NK];        // (k,n) -> global slot
__device__ int  g_ulist[NK];        // global slot -> n
__device__ int  g_kbase[KOFF + 1];  // slot range per k
__device__ int  g_hist[NVOX];
__device__ int  g_off [NVOX + 1];
__device__ int  g_cursor[NVOX];
__device__ int  g_entries[MAXPAIR]; // CSR payload: slot ids (43 MB)
__device__ int  g_part1[NB_USED];
__device__ int  g_part2[NB_HIST];

// ---------------- f32x2 helpers ----------------
__device__ __forceinline__ ull pack2(float x) {
    ull r; asm("mov.b64 %0, {%1, %1};" : "=l"(r) : "f"(x)); return r;
}
__device__ __forceinline__ void fma2(ull& acc, ull a, ull b) {
    asm("fma.rn.f32x2 %0, %1, %2, %0;" : "+l"(acc) : "l"(a), "l"(b));
}
__device__ __forceinline__ void add2(ull& acc, ull v) {
    asm("add.rn.f32x2 %0, %0, %1;" : "+l"(acc) : "l"(v));
}

// ---------------- detect idx dtype + reset counters ----------------
__global__ void detect_kernel(const unsigned* __restrict__ idx_words) {
    int t = threadIdx.x;
    if (t < KOFF) g_cnt[t] = 0;
    if (t == 63) {
        int is64 = 1;
        #pragma unroll 1
        for (int i = 0; i < 64; i++)
            if (idx_words[2 * i + 1] != 0u) { is64 = 0; break; }
        g_is64 = is64;
    }
}

// ---------------- zero used flags + histogram ----------------
__global__ void zero_kernel() {
    int i = blockIdx.x * blockDim.x + threadIdx.x;
    int stride = gridDim.x * blockDim.x;
    ull* u8w = (ull*)g_used;                 // NK/8 = 675000 words
    for (int j = i; j < NK / 8; j += stride) u8w[j] = 0ull;
    for (int j = i; j < NVOX; j += stride) g_hist[j] = 0;
}

// ---------------- compact valid pairs + mark used rows + out-hist ----------------
__global__ void compact_kernel(const void* __restrict__ in_idx,
                               const void* __restrict__ out_idx,
                               const float* __restrict__ mask) {
    int k = blockIdx.y;
    int p = blockIdx.x * blockDim.x + threadIdx.x;
    int is64 = g_is64;

    bool valid = false;
    int vi = 0, vo = 0;
    if (p < PPK) {
        size_t g = (size_t)k * PPK + p;
        valid = mask[g] > 0.5f;
        if (valid) {
            if (is64) {
                vi = (int)((const long long*)in_idx)[g];
                vo = (int)((const long long*)out_idx)[g];
            } else {
                vi = ((const int*)in_idx)[g];
                vo = ((const int*)out_idx)[g];
            }
        }
    }
    unsigned b = __ballot_sync(0xffffffffu, valid);
    int lane = threadIdx.x & 31;
    int cntw = __popc(b);
    int pref = __popc(b & ((1u << lane) - 1u));
    int base = 0;
    if (lane == 0 && cntw) base = atomicAdd(&g_cnt[k], cntw);
    base = __shfl_sync(0xffffffffu, base, 0);
    if (valid) {
        g_pairs[(size_t)k * PPK + base + pref] = make_int2(vi, vo);
        g_used[(size_t)k * NVOX + vi] = 1;
        atomicAdd(&g_hist[vo], 1);
    }
}

// ---------------- scans ----------------
__global__ void scanA_used() {
    __shared__ int sm[256];
    int t = threadIdx.x;
    int widx = blockIdx.x * 256 + t;        // ull word index
    ull v = (widx < NK / 8) ? ((const ull*)g_used)[widx] : 0ull;
    int s = (int)((v * 0x0101010101010101ULL) >> 56);
    sm[t] = s; __syncthreads();
    for (int d = 128; d > 0; d >>= 1) {
        if (t < d) sm[t] += sm[t + d];
        __syncthreads();
    }
    if (t == 0) g_part1[blockIdx.x] = sm[0];
}

__global__ void scanA_hist() {
    __shared__ int sm[256];
    int t = threadIdx.x;
    int base = blockIdx.x * SCAN_BLK + t * 8;
    int s = 0;
    #pragma unroll
    for (int i = 0; i < 8; i++) {
        int idx = base + i;
        if (idx < NVOX) s += g_hist[idx];
    }
    sm[t] = s; __syncthreads();
    for (int d = 128; d > 0; d >>= 1) {
        if (t < d) sm[t] += sm[t + d];
        __syncthreads();
    }
    if (t == 0) g_part2[blockIdx.x] = sm[0];
}

__device__ void scan_mid_dev(int* part, int n, int* total_store) {
    __shared__ int sm[1024];
    __shared__ int sbase;
    int t = threadIdx.x;
    if (t == 0) sbase = 0;
    __syncthreads();
    for (int s0 = 0; s0 < n; s0 += 1024) {
        int i = s0 + t;
        int v = (i < n) ? part[i] : 0;
        sm[t] = v; __syncthreads();
        #pragma unroll
        for (int d = 1; d < 1024; d <<= 1) {
            int x = (t >= d) ? sm[t - d] : 0;
            __syncthreads();
            sm[t] += x;
            __syncthreads();
        }
        int incl = sm[t];
        int b = sbase;
        if (i < n) part[i] = b + incl - v;   // exclusive
        __syncthreads();
        if (t == 1023) sbase = b + sm[1023];
        __syncthreads();
    }
    if (t == 0 && total_store) *total_store = sbase;
}
__global__ void scanB_used() { scan_mid_dev(g_part1, NB_USED, &g_kbase[KOFF]); }
__global__ void scanB_hist() { scan_mid_dev(g_part2, NB_HIST, &g_off[NVOX]); }

__device__ __forceinline__ int block_excl_scan(int s, int* sm) {
    int t = threadIdx.x;
    sm[t] = s; __syncthreads();
    #pragma unroll
    for (int d = 1; d < 256; d <<= 1) {
        int x = (t >= d) ? sm[t - d] : 0;
        __syncthreads();
        sm[t] += x;
        __syncthreads();
    }
    return sm[t] - s;
}

__global__ void scanC_used() {
    __shared__ int sm[256];
    int t = threadIdx.x;
    int widx = blockIdx.x * 256 + t;
    ull v = (widx < NK / 8) ? ((const ull*)g_used)[widx] : 0ull;
    int s = (int)((v * 0x0101010101010101ULL) >> 56);
    int excl = block_excl_scan(s, sm);
    int g = g_part1[blockIdx.x] + excl;
    if (widx < NK / 8) {
        int idx = widx * 8;
        #pragma unroll
        for (int i = 0; i < 8; i++) {
            int id = idx + i;
            if ((id % NVOX) == 0) g_kbase[id / NVOX] = g;
            if ((v >> (8 * i)) & 1ull) {
                g_uslot[id] = g;
                g_ulist[g] = id % NVOX;
                g++;
            }
        }
    }
}

__global__ void scanC_hist() {
    __shared__ int sm[256];
    int t = threadIdx.x;
    int base = blockIdx.x * SCAN_BLK + t * 8;
    int vals[8]; int s = 0;
    #pragma unroll
    for (int i = 0; i < 8; i++) {
        int idx = base + i;
        vals[i] = (idx < NVOX) ? g_hist[idx] : 0;
        s += vals[i];
    }
    int excl = block_excl_scan(s, sm);
    int g = g_part2[blockIdx.x] + excl;
    #pragma unroll
    for (int i = 0; i < 8; i++) {
        int idx = base + i;
        if (idx < NVOX) { g_off[idx] = g; g_cursor[idx] = g; }
        g += vals[i];
    }
}

// ---------------- CSR fill: entries sorted by out voxel ----------------
__global__ void csr_fill() {
    int k = blockIdx.y;
    int i = blockIdx.x * blockDim.x + threadIdx.x;
    if (i >= g_cnt[k]) return;
    int2 pr = g_pairs[(size_t)k * PPK + i];
    int slot = g_uslot[(size_t)k * NVOX + pr.x];
    int pos = atomicAdd(&g_cursor[pr.y], 1);
    g_entries[pos] = slot;
}

// ---------------- GEMM1: T[slot] = feats[ulist[slot]] @ W_in[k] ----------------
// block = 128 rows x 64 ch, K=32; 128 threads, thread tile 8x8
__global__ void __launch_bounds__(128)
gemm1_kernel(const float* __restrict__ feats, const float* __restrict__ W) {
    __shared__ __align__(16) float Xs[CIN * 132];
    __shared__ __align__(16) ull   Wsh[CIN * CMID / 2];

    const int k = blockIdx.y;
    const int kb = g_kbase[k];
    const int ucnt = g_kbase[k + 1] - kb;
    const int base = blockIdx.x * 128;
    if (base >= ucnt) return;
    const int tid = threadIdx.x;

    {   // W tile
        const float4* Wk = (const float4*)(W + (size_t)k * CIN * CMID);
        float4* Wd = (float4*)Wsh;
        #pragma unroll
        for (int i = 0; i < 4; i++) Wd[tid + i * 128] = Wk[tid + i * 128];
    }

    // coalesced gather staging: 8 threads per row, transposed store
    {
        const int j = tid & 7, grp = tid >> 3;     // grp 0..15
        #pragma unroll
        for (int s = 0; s < 8; s++) {
            int p = s * 16 + grp;                  // row in tile
            int n = (base + p < ucnt) ? g_ulist[kb + base + p] : 0;
            float4 v = __ldg((const float4*)(feats + (size_t)n * CIN) + j);
            int c = 4 * j;
            Xs[(c + 0) * 132 + p] = v.x;
            Xs[(c + 1) * 132 + p] = v.y;
            Xs[(c + 2) * 132 + p] = v.z;
            Xs[(c + 3) * 132 + p] = v.w;
        }
    }
    __syncthreads();

    const int tx = tid & 7, ty = tid >> 3;
    const int ty8 = ty * 8, tx4 = tx * 4;

    ull acc[8][4];
    #pragma unroll
    for (int i = 0; i < 8; i++)
        #pragma unroll
        for (int j = 0; j < 4; j++) acc[i][j] = 0ull;

    #pragma unroll 8
    for (int kk = 0; kk < CIN; kk++) {
        const float4 xa = *(const float4*)&Xs[kk * 132 + ty8];
        const float4 xb = *(const float4*)&Xs[kk * 132 + ty8 + 4];
        const ulonglong2 wa = *(const ulonglong2*)&Wsh[kk * 32 + tx4];
        const ulonglong2 wb = *(const ulonglong2*)&Wsh[kk * 32 + tx4 + 2];
        ull xp[8];
        xp[0] = pack2(xa.x); xp[1] = pack2(xa.y);
        xp[2] = pack2(xa.z); xp[3] = pack2(xa.w);
        xp[4] = pack2(xb.x); xp[5] = pack2(xb.y);
        xp[6] = pack2(xb.z); xp[7] = pack2(xb.w);
        #pragma unroll
        for (int i = 0; i < 8; i++) {
            fma2(acc[i][0], xp[i], wa.x);
            fma2(acc[i][1], xp[i], wa.y);
            fma2(acc[i][2], xp[i], wb.x);
            fma2(acc[i][3], xp[i], wb.y);
        }
    }

    // plain stores (no atomics)
    #pragma unroll
    for (int i = 0; i < 8; i++) {
        int p = ty8 + i;
        if (base + p < ucnt) {
            ull* tp = (ull*)(g_T + (size_t)(kb + base + p) * CMID) + tx4;
            *(ulonglong2*)(tp)     = make_ulonglong2(acc[i][0], acc[i][1]);
            *(ulonglong2*)(tp + 2) = make_ulonglong2(acc[i][2], acc[i][3]);
        }
    }
}

// ---------------- route1: g_h[o] = sum of T rows (CSR, CMID stride) ----------------
__global__ void route1_kernel() {
    int w = (blockIdx.x * blockDim.x + threadIdx.x) >> 5;
    int lane = threadIdx.x & 31;
    if (w >= NVOX) return;
    int e = g_off[w], e1 = g_off[w + 1];
    ull acc = 0ull;
    for (; e + 4 <= e1; e += 4) {
        int r0 = __ldg(&g_entries[e]);
        int r1 = __ldg(&g_entries[e + 1]);
        int r2 = __ldg(&g_entries[e + 2]);
        int r3 = __ldg(&g_entries[e + 3]);
        ull v0 = __ldg((const ull*)(g_T + (size_t)r0 * CMID) + lane);
        ull v1 = __ldg((const ull*)(g_T + (size_t)r1 * CMID) + lane);
        ull v2 = __ldg((const ull*)(g_T + (size_t)r2 * CMID) + lane);
        ull v3 = __ldg((const ull*)(g_T + (size_t)r3 * CMID) + lane);
        add2(acc, v0); add2(acc, v1); add2(acc, v2); add2(acc, v3);
    }
    for (; e < e1; e++) {
        int r = __ldg(&g_entries[e]);
        add2(acc, __ldg((const ull*)(g_T + (size_t)r * CMID) + lane));
    }
    *((ull*)(g_h + (size_t)w * CMID) + lane) = acc;
}

// ---------------- GEMM2: T[slot] = relu(g_h[ulist[slot]]) @ W_out[k] ------------
// (overwrites g_T with COUT-stride rows; layer-1 data is dead by now)
// block = 128 rows x 32 ch, K=64; 128 threads, thread tile 4x8
__global__ void __launch_bounds__(128)
gemm2_kernel(const float* __restrict__ W) {
    __shared__ __align__(16) float Xs[CMID * 132];
    __shared__ __align__(16) ull   Wsh[CMID * COUT / 2];

    const int k = blockIdx.y;
    const int kb = g_kbase[k];
    const int ucnt = g_kbase[k + 1] - kb;
    const int base = blockIdx.x * 128;
    if (base >= ucnt) return;
    const int tid = threadIdx.x;

    {   // W tile (2048 floats)
        const float4* Wk = (const float4*)(W + (size_t)k * CMID * COUT);
        float4* Wd = (float4*)Wsh;
        #pragma unroll
        for (int i = 0; i < 4; i++) Wd[tid + i * 128] = Wk[tid + i * 128];
    }

    // staging with fused ReLU: 8 threads per row, 2 float4 each
    {
        const int j = tid & 7, grp = tid >> 3;
        #pragma unroll
        for (int s = 0; s < 8; s++) {
            int p = s * 16 + grp;
            int n = (base + p < ucnt) ? g_ulist[kb + base + p] : 0;
            const float4* hr = (const float4*)(g_h + (size_t)n * CMID);
            #pragma unroll
            for (int hh = 0; hh < 2; hh++) {
                float4 v = __ldg(hr + j + hh * 8);
                v.x = fmaxf(v.x, 0.f); v.y = fmaxf(v.y, 0.f);
                v.z = fmaxf(v.z, 0.f); v.w = fmaxf(v.w, 0.f);
                int c = 4 * j + hh * 32;
                Xs[(c + 0) * 132 + p] = v.x;
                Xs[(c + 1) * 132 + p] = v.y;
                Xs[(c + 2) * 132 + p] = v.z;
                Xs[(c + 3) * 132 + p] = v.w;
            }
        }
    }
    __syncthreads();

    const int tx = tid & 3, ty = tid >> 2;      // tx: 8ch, ty: 4 rows
    const int ty4 = ty * 4, tx4 = tx * 4;

    ull acc[4][4];
    #pragma unroll
    for (int i = 0; i < 4; i++)
        #pragma unroll
        for (int j = 0; j < 4; j++) acc[i][j] = 0ull;

    #pragma unroll 8
    for (int kk = 0; kk < CMID; kk++) {
        const float4 xa = *(const float4*)&Xs[kk * 132 + ty4];
        const ulonglong2 wa = *(const ulonglong2*)&Wsh[kk * 16 + tx4];
        const ulonglong2 wb = *(const ulonglong2*)&Wsh[kk * 16 + tx4 + 2];
        ull xp[4];
        xp[0] = pack2(xa.x); xp[1] = pack2(xa.y);
        xp[2] = pack2(xa.z); xp[3] = pack2(xa.w);
        #pragma unroll
        for (int i = 0; i < 4; i++) {
            fma2(acc[i][0], xp[i], wa.x);
            fma2(acc[i][1], xp[i], wa.y);
            fma2(acc[i][2], xp[i], wb.x);
            fma2(acc[i][3], xp[i], wb.y);
        }
    }

    #pragma unroll
    for (int i = 0; i < 4; i++) {
        int p = ty4 + i;
        if (base + p < ucnt) {
            ull* tp = (ull*)(g_T + (size_t)(kb + base + p) * COUT) + tx4;
            *(ulonglong2*)(tp)     = make_ulonglong2(acc[i][0], acc[i][1]);
            *(ulonglong2*)(tp + 2) = make_ulonglong2(acc[i][2], acc[i][3]);
        }
    }
}

// ---------------- route2: out[o] = sum of T rows (CSR, COUT stride) -------------
__global__ void route2_kernel(float* __restrict__ out) {
    int w = (blockIdx.x * blockDim.x + threadIdx.x) >> 5;
    int lane = threadIdx.x & 31;
    if (w >= NVOX) return;
    int e = g_off[w], e1 = g_off[w + 1];
    float acc = 0.f;
    for (; e + 4 <= e1; e += 4) {
        int r0 = __ldg(&g_entries[e]);
        int r1 = __ldg(&g_entries[e + 1]);
        int r2 = __ldg(&g_entries[e + 2]);
        int r3 = __ldg(&g_entries[e + 3]);
        float v0 = __ldg(g_T + (size_t)r0 * COUT + lane);
        float v1 = __ldg(g_T + (size_t)r1 * COUT + lane);
        float v2 = __ldg(g_T + (size_t)r2 * COUT + lane);
        float v3 = __ldg(g_T + (size_t)r3 * COUT + lane);
        acc += v0 + v1 + v2 + v3;
    }
    for (; e < e1; e++) {
        int r = __ldg(&g_entries[e]);
        acc += __ldg(g_T + (size_t)r * COUT + lane);
    }
    out[(size_t)w * COUT + lane] = acc;
}

// ---------------- launch ----------------
extern "C" void kernel_launch(void* const* d_in, const int* in_sizes, int n_in,
                              void* d_out, int out_size) {
    const float* feats   = (const float*)d_in[0];
    const void*  in_idx  = d_in[1];
    const void*  out_idx = d_in[2];
    const float* mask    = (const float*)d_in[3];
    const float* W_in    = (const float*)d_in[4];
    const float* W_out   = (const float*)d_in[5];
    float* out = (float*)d_out;

    detect_kernel<<<1, 64>>>((const unsigned*)in_idx);
    zero_kernel<<<2048, 256>>>();

    dim3 cg((PPK + 255) / 256, KOFF);
    compact_kernel<<<cg, 256>>>(in_idx, out_idx, mask);

    scanA_used<<<NB_USED, 256>>>();
    scanB_used<<<1, 1024>>>();
    scanC_used<<<NB_USED, 256>>>();

    scanA_hist<<<NB_HIST, 256>>>();
    scanB_hist<<<1, 1024>>>();
    scanC_hist<<<NB_HIST, 256>>>();

    csr_fill<<<cg, 256>>>();

    dim3 gg((NVOX + 127) / 128, KOFF);
    gemm1_kernel<<<gg, 128>>>(feats, W_in);
    route1_kernel<<<(NVOX * 32 + 255) / 256, 256>>>();
    gemm2_kernel<<<gg, 128>>>(W_out);
    route2_kernel<<<(NVOX * 32 + 255) / 256, 256>>>(out);
}

// round 7
// speedup vs baseline: 1.4700x; 1.0012x over previous
#include <cuda_runtime.h>
#include <stdint.h>

#define NVOX 200000
#define KOFF 27
#define PPK  400000
#define CIN  32
#define CMID 64
#define COUT 32
#define NK   (KOFF * NVOX)            /* 5,400,000 (k,n) slot space */
#define MAXPAIR (KOFF * PPK)          /* 10.8M worst-case valid pairs */

#define SCAN_BLK 2048
#define NB_USED ((NK + SCAN_BLK - 1) / SCAN_BLK)     /* 2637 */
#define NB_HIST ((NVOX + SCAN_BLK - 1) / SCAN_BLK)   /* 98   */

typedef unsigned long long ull;

// ---------------- static scratch (no runtime allocs; < 2GB total for linker) ----
// g_T serves as T1 (NK x CMID, layer-1 contributions) then is REUSED as
// T2 (NK x COUT, layer-2 contributions). Sequential dataflow makes this safe:
// gemm1->T, route1 reads T (then dead), gemm2 overwrites T, route2 reads T.
__device__ __align__(16) float g_T [(size_t)NK * CMID];       // 1.38 GB
__device__ __align__(16) float g_h [(size_t)NVOX * CMID];     // 51 MB
__device__ __align__(16) int2  g_pairs[(size_t)MAXPAIR];      // 86 MB
__device__ int  g_cnt[KOFF];
__device__ int  g_is64;
__device__ unsigned char g_used[NK];                          // 5.4 MB
__device__ int  g_uslot[NK];        // (k,n) -> global slot
__device__ int  g_ulist[NK];        // global slot -> n
__device__ int  g_kbase[KOFF + 1];  // slot range per k
__device__ int  g_hist[NVOX];
__device__ int  g_off [NVOX + 1];
__device__ int  g_cursor[NVOX];
__device__ int  g_entries[MAXPAIR]; // CSR payload: slot ids (43 MB)
__device__ int  g_part1[NB_USED];
__device__ int  g_part2[NB_HIST];

// ---------------- f32x2 helpers ----------------
__device__ __forceinline__ ull pack2(float x) {
    ull r; asm("mov.b64 %0, {%1, %1};" : "=l"(r) : "f"(x)); return r;
}
__device__ __forceinline__ void fma2(ull& acc, ull a, ull b) {
    asm("fma.rn.f32x2 %0, %1, %2, %0;" : "+l"(acc) : "l"(a), "l"(b));
}
__device__ __forceinline__ void add2(ull& acc, ull v) {
    asm("add.rn.f32x2 %0, %0, %1;" : "+l"(acc) : "l"(v));
}

// ---------------- detect idx dtype + reset counters ----------------
__global__ void detect_kernel(const unsigned* __restrict__ idx_words) {
    int t = threadIdx.x;
    if (t < KOFF) g_cnt[t] = 0;
    if (t == 63) {
        int is64 = 1;
        #pragma unroll 1
        for (int i = 0; i < 64; i++)
            if (idx_words[2 * i + 1] != 0u) { is64 = 0; break; }
        g_is64 = is64;
    }
}

// ---------------- zero used flags + histogram ----------------
__global__ void zero_kernel() {
    int i = blockIdx.x * blockDim.x + threadIdx.x;
    int stride = gridDim.x * blockDim.x;
    ull* u8w = (ull*)g_used;                 // NK/8 = 675000 words
    for (int j = i; j < NK / 8; j += stride) u8w[j] = 0ull;
    for (int j = i; j < NVOX; j += stride) g_hist[j] = 0;
}

// ---------------- compact valid pairs + mark used rows + out-hist ----------------
__global__ void compact_kernel(const void* __restrict__ in_idx,
                               const void* __restrict__ out_idx,
                               const float* __restrict__ mask) {
    int k = blockIdx.y;
    int p = blockIdx.x * blockDim.x + threadIdx.x;
    int is64 = g_is64;

    bool valid = false;
    int vi = 0, vo = 0;
    if (p < PPK) {
        size_t g = (size_t)k * PPK + p;
        valid = mask[g] > 0.5f;
        if (valid) {
            if (is64) {
                vi = (int)((const long long*)in_idx)[g];
                vo = (int)((const long long*)out_idx)[g];
            } else {
                vi = ((const int*)in_idx)[g];
                vo = ((const int*)out_idx)[g];
            }
        }
    }
    unsigned b = __ballot_sync(0xffffffffu, valid);
    int lane = threadIdx.x & 31;
    int cntw = __popc(b);
    int pref = __popc(b & ((1u << lane) - 1u));
    int base = 0;
    if (lane == 0 && cntw) base = atomicAdd(&g_cnt[k], cntw);
    base = __shfl_sync(0xffffffffu, base, 0);
    if (valid) {
        g_pairs[(size_t)k * PPK + base + pref] = make_int2(vi, vo);
        g_used[(size_t)k * NVOX + vi] = 1;
        atomicAdd(&g_hist[vo], 1);
    }
}

// ---------------- scans ----------------
__global__ void scanA_used() {
    __shared__ int sm[256];
    int t = threadIdx.x;
    int widx = blockIdx.x * 256 + t;        // ull word index
    ull v = (widx < NK / 8) ? ((const ull*)g_used)[widx] : 0ull;
    int s = (int)((v * 0x0101010101010101ULL) >> 56);
    sm[t] = s; __syncthreads();
    for (int d = 128; d > 0; d >>= 1) {
        if (t < d) sm[t] += sm[t + d];
        __syncthreads();
    }
    if (t == 0) g_part1[blockIdx.x] = sm[0];
}

__global__ void scanA_hist() {
    __shared__ int sm[256];
    int t = threadIdx.x;
    int base = blockIdx.x * SCAN_BLK + t * 8;
    int s = 0;
    #pragma unroll
    for (int i = 0; i < 8; i++) {
        int idx = base + i;
        if (idx < NVOX) s += g_hist[idx];
    }
    sm[t] = s; __syncthreads();
    for (int d = 128; d > 0; d >>= 1) {
        if (t < d) sm[t] += sm[t + d];
        __syncthreads();
    }
    if (t == 0) g_part2[blockIdx.x] = sm[0];
}

__device__ void scan_mid_dev(int* part, int n, int* total_store) {
    __shared__ int sm[1024];
    __shared__ int sbase;
    int t = threadIdx.x;
    if (t == 0) sbase = 0;
    __syncthreads();
    for (int s0 = 0; s0 < n; s0 += 1024) {
        int i = s0 + t;
        int v = (i < n) ? part[i] : 0;
        sm[t] = v; __syncthreads();
        #pragma unroll
        for (int d = 1; d < 1024; d <<= 1) {
            int x = (t >= d) ? sm[t - d] : 0;
            __syncthreads();
            sm[t] += x;
            __syncthreads();
        }
        int incl = sm[t];
        int b = sbase;
        if (i < n) part[i] = b + incl - v;   // exclusive
        __syncthreads();
        if (t == 1023) sbase = b + sm[1023];
        __syncthreads();
    }
    if (t == 0 && total_store) *total_store = sbase;
}
__global__ void scanB_used() { scan_mid_dev(g_part1, NB_USED, &g_kbase[KOFF]); }
__global__ void scanB_hist() { scan_mid_dev(g_part2, NB_HIST, &g_off[NVOX]); }

__device__ __forceinline__ int block_excl_scan(int s, int* sm) {
    int t = threadIdx.x;
    sm[t] = s; __syncthreads();
    #pragma unroll
    for (int d = 1; d < 256; d <<= 1) {
        int x = (t >= d) ? sm[t - d] : 0;
        __syncthreads();
        sm[t] += x;
        __syncthreads();
    }
    return sm[t] - s;
}

__global__ void scanC_used() {
    __shared__ int sm[256];
    int t = threadIdx.x;
    int widx = blockIdx.x * 256 + t;
    ull v = (widx < NK / 8) ? ((const ull*)g_used)[widx] : 0ull;
    int s = (int)((v * 0x0101010101010101ULL) >> 56);
    int excl = block_excl_scan(s, sm);
    int g = g_part1[blockIdx.x] + excl;
    if (widx < NK / 8) {
        int idx = widx * 8;
        #pragma unroll
        for (int i = 0; i < 8; i++) {
            int id = idx + i;
            if ((id % NVOX) == 0) g_kbase[id / NVOX] = g;
            if ((v >> (8 * i)) & 1ull) {
                g_uslot[id] = g;
                g_ulist[g] = id % NVOX;
                g++;
            }
        }
    }
}

__global__ void scanC_hist() {
    __shared__ int sm[256];
    int t = threadIdx.x;
    int base = blockIdx.x * SCAN_BLK + t * 8;
    int vals[8]; int s = 0;
    #pragma unroll
    for (int i = 0; i < 8; i++) {
        int idx = base + i;
        vals[i] = (idx < NVOX) ? g_hist[idx] : 0;
        s += vals[i];
    }
    int excl = block_excl_scan(s, sm);
    int g = g_part2[blockIdx.x] + excl;
    #pragma unroll
    for (int i = 0; i < 8; i++) {
        int idx = base + i;
        if (idx < NVOX) { g_off[idx] = g; g_cursor[idx] = g; }
        g += vals[i];
    }
}

// ---------------- CSR fill: entries sorted by out voxel ----------------
__global__ void csr_fill() {
    int k = blockIdx.y;
    int i = blockIdx.x * blockDim.x + threadIdx.x;
    if (i >= g_cnt[k]) return;
    int2 pr = g_pairs[(size_t)k * PPK + i];
    int slot = g_uslot[(size_t)k * NVOX + pr.x];
    int pos = atomicAdd(&g_cursor[pr.y], 1);
    g_entries[pos] = slot;
}

// ---------------- GEMM1: T[slot] = feats[ulist[slot]] @ W_in[k] ----------------
// block = 128 rows x 64 ch, K=32; 128 threads, thread tile 8x8
__global__ void __launch_bounds__(128)
gemm1_kernel(const float* __restrict__ feats, const float* __restrict__ W) {
    __shared__ __align__(16) float Xs[CIN * 132];
    __shared__ __align__(16) ull   Wsh[CIN * CMID / 2];

    const int k = blockIdx.y;
    const int kb = g_kbase[k];
    const int ucnt = g_kbase[k + 1] - kb;
    const int base = blockIdx.x * 128;
    if (base >= ucnt) return;
    const int tid = threadIdx.x;

    {   // W tile
        const float4* Wk = (const float4*)(W + (size_t)k * CIN * CMID);
        float4* Wd = (float4*)Wsh;
        #pragma unroll
        for (int i = 0; i < 4; i++) Wd[tid + i * 128] = Wk[tid + i * 128];
    }

    // coalesced gather staging: 8 threads per row, transposed store
    {
        const int j = tid & 7, grp = tid >> 3;     // grp 0..15
        #pragma unroll
        for (int s = 0; s < 8; s++) {
            int p = s * 16 + grp;                  // row in tile
            int n = (base + p < ucnt) ? g_ulist[kb + base + p] : 0;
            float4 v = __ldg((const float4*)(feats + (size_t)n * CIN) + j);
            int c = 4 * j;
            Xs[(c + 0) * 132 + p] = v.x;
            Xs[(c + 1) * 132 + p] = v.y;
            Xs[(c + 2) * 132 + p] = v.z;
            Xs[(c + 3) * 132 + p] = v.w;
        }
    }
    __syncthreads();

    const int tx = tid & 7, ty = tid >> 3;
    const int ty8 = ty * 8, tx4 = tx * 4;

    ull acc[8][4];
    #pragma unroll
    for (int i = 0; i < 8; i++)
        #pragma unroll
        for (int j = 0; j < 4; j++) acc[i][j] = 0ull;

    #pragma unroll 8
    for (int kk = 0; kk < CIN; kk++) {
        const float4 xa = *(const float4*)&Xs[kk * 132 + ty8];
        const float4 xb = *(const float4*)&Xs[kk * 132 + ty8 + 4];
        const ulonglong2 wa = *(const ulonglong2*)&Wsh[kk * 32 + tx4];
        const ulonglong2 wb = *(const ulonglong2*)&Wsh[kk * 32 + tx4 + 2];
        ull xp[8];
        xp[0] = pack2(xa.x); xp[1] = pack2(xa.y);
        xp[2] = pack2(xa.z); xp[3] = pack2(xa.w);
        xp[4] = pack2(xb.x); xp[5] = pack2(xb.y);
        xp[6] = pack2(xb.z); xp[7] = pack2(xb.w);
        #pragma unroll
        for (int i = 0; i < 8; i++) {
            fma2(acc[i][0], xp[i], wa.x);
            fma2(acc[i][1], xp[i], wa.y);
            fma2(acc[i][2], xp[i], wb.x);
            fma2(acc[i][3], xp[i], wb.y);
        }
    }

    // plain stores (no atomics)
    #pragma unroll
    for (int i = 0; i < 8; i++) {
        int p = ty8 + i;
        if (base + p < ucnt) {
            ull* tp = (ull*)(g_T + (size_t)(kb + base + p) * CMID) + tx4;
            *(ulonglong2*)(tp)     = make_ulonglong2(acc[i][0], acc[i][1]);
            *(ulonglong2*)(tp + 2) = make_ulonglong2(acc[i][2], acc[i][3]);
        }
    }
}

// ---------------- route1: g_h[o] = sum of T rows (CSR, CMID stride) ----------------
__global__ void route1_kernel() {
    int w = (blockIdx.x * blockDim.x + threadIdx.x) >> 5;
    int lane = threadIdx.x & 31;
    if (w >= NVOX) return;
    int e = g_off[w], e1 = g_off[w + 1];
    ull acc = 0ull;
    for (; e + 4 <= e1; e += 4) {
        int r0 = __ldg(&g_entries[e]);
        int r1 = __ldg(&g_entries[e + 1]);
        int r2 = __ldg(&g_entries[e + 2]);
        int r3 = __ldg(&g_entries[e + 3]);
        ull v0 = __ldg((const ull*)(g_T + (size_t)r0 * CMID) + lane);
        ull v1 = __ldg((const ull*)(g_T + (size_t)r1 * CMID) + lane);
        ull v2 = __ldg((const ull*)(g_T + (size_t)r2 * CMID) + lane);
        ull v3 = __ldg((const ull*)(g_T + (size_t)r3 * CMID) + lane);
        add2(acc, v0); add2(acc, v1); add2(acc, v2); add2(acc, v3);
    }
    for (; e < e1; e++) {
        int r = __ldg(&g_entries[e]);
        add2(acc, __ldg((const ull*)(g_T + (size_t)r * CMID) + lane));
    }
    *((ull*)(g_h + (size_t)w * CMID) + lane) = acc;
}

// ---------------- GEMM2: T[slot] = relu(g_h[ulist[slot]]) @ W_out[k] ------------
// (overwrites g_T with COUT-stride rows; layer-1 data is dead by now)
// block = 128 rows x 32 ch, K=64; 128 threads, thread tile 4x8
__global__ void __launch_bounds__(128)
gemm2_kernel(const float* __restrict__ W) {
    __shared__ __align__(16) float Xs[CMID * 132];
    __shared__ __align__(16) ull   Wsh[CMID * COUT / 2];

    const int k = blockIdx.y;
    const int kb = g_kbase[k];
    const int ucnt = g_kbase[k + 1] - kb;
    const int base = blockIdx.x * 128;
    if (base >= ucnt) return;
    const int tid = threadIdx.x;

    {   // W tile (2048 floats)
        const float4* Wk = (const float4*)(W + (size_t)k * CMID * COUT);
        float4* Wd = (float4*)Wsh;
        #pragma unroll
        for (int i = 0; i < 4; i++) Wd[tid + i * 128] = Wk[tid + i * 128];
    }

    // staging with fused ReLU: 8 threads per row, 2 float4 each
    {
        const int j = tid & 7, grp = tid >> 3;
        #pragma unroll
        for (int s = 0; s < 8; s++) {
            int p = s * 16 + grp;
            int n = (base + p < ucnt) ? g_ulist[kb + base + p] : 0;
            const float4* hr = (const float4*)(g_h + (size_t)n * CMID);
            #pragma unroll
            for (int hh = 0; hh < 2; hh++) {
                float4 v = __ldg(hr + j + hh * 8);
                v.x = fmaxf(v.x, 0.f); v.y = fmaxf(v.y, 0.f);
                v.z = fmaxf(v.z, 0.f); v.w = fmaxf(v.w, 0.f);
                int c = 4 * j + hh * 32;
                Xs[(c + 0) * 132 + p] = v.x;
                Xs[(c + 1) * 132 + p] = v.y;
                Xs[(c + 2) * 132 + p] = v.z;
                Xs[(c + 3) * 132 + p] = v.w;
            }
        }
    }
    __syncthreads();

    const int tx = tid & 3, ty = tid >> 2;      // tx: 8ch, ty: 4 rows
    const int ty4 = ty * 4, tx4 = tx * 4;

    ull acc[4][4];
    #pragma unroll
    for (int i = 0; i < 4; i++)
        #pragma unroll
        for (int j = 0; j < 4; j++) acc[i][j] = 0ull;

    #pragma unroll 8
    for (int kk = 0; kk < CMID; kk++) {
        const float4 xa = *(const float4*)&Xs[kk * 132 + ty4];
        const ulonglong2 wa = *(const ulonglong2*)&Wsh[kk * 16 + tx4];
        const ulonglong2 wb = *(const ulonglong2*)&Wsh[kk * 16 + tx4 + 2];
        ull xp[4];
        xp[0] = pack2(xa.x); xp[1] = pack2(xa.y);
        xp[2] = pack2(xa.z); xp[3] = pack2(xa.w);
        #pragma unroll
        for (int i = 0; i < 4; i++) {
            fma2(acc[i][0], xp[i], wa.x);
            fma2(acc[i][1], xp[i], wa.y);
            fma2(acc[i][2], xp[i], wb.x);
            fma2(acc[i][3], xp[i], wb.y);
        }
    }

    #pragma unroll
    for (int i = 0; i < 4; i++) {
        int p = ty4 + i;
        if (base + p < ucnt) {
            ull* tp = (ull*)(g_T + (size_t)(kb + base + p) * COUT) + tx4;
            *(ulonglong2*)(tp)     = make_ulonglong2(acc[i][0], acc[i][1]);
            *(ulonglong2*)(tp + 2) = make_ulonglong2(acc[i][2], acc[i][3]);
        }
    }
}

// ---------------- route2: out[o] = sum of T rows (CSR, COUT stride) -------------
__global__ void route2_kernel(float* __restrict__ out) {
    int w = (blockIdx.x * blockDim.x + threadIdx.x) >> 5;
    int lane = threadIdx.x & 31;
    if (w >= NVOX) return;
    int e = g_off[w], e1 = g_off[w + 1];
    float acc = 0.f;
    for (; e + 4 <= e1; e += 4) {
        int r0 = __ldg(&g_entries[e]);
        int r1 = __ldg(&g_entries[e + 1]);
        int r2 = __ldg(&g_entries[e + 2]);
        int r3 = __ldg(&g_entries[e + 3]);
        float v0 = __ldg(g_T + (size_t)r0 * COUT + lane);
        float v1 = __ldg(g_T + (size_t)r1 * COUT + lane);
        float v2 = __ldg(g_T + (size_t)r2 * COUT + lane);
        float v3 = __ldg(g_T + (size_t)r3 * COUT + lane);
        acc += v0 + v1 + v2 + v3;
    }
    for (; e < e1; e++) {
        int r = __ldg(&g_entries[e]);
        acc += __ldg(g_T + (size_t)r * COUT + lane);
    }
    out[(size_t)w * COUT + lane] = acc;
}

// ---------------- launch ----------------
extern "C" void kernel_launch(void* const* d_in, const int* in_sizes, int n_in,
                              void* d_out, int out_size) {
    const float* feats   = (const float*)d_in[0];
    const void*  in_idx  = d_in[1];
    const void*  out_idx = d_in[2];
    const float* mask    = (const float*)d_in[3];
    const float* W_in    = (const float*)d_in[4];
    const float* W_out   = (const float*)d_in[5];
    float* out = (float*)d_out;

    detect_kernel<<<1, 64>>>((const unsigned*)in_idx);
    zero_kernel<<<2048, 256>>>();

    dim3 cg((PPK + 255) / 256, KOFF);
    compact_kernel<<<cg, 256>>>(in_idx, out_idx, mask);

    scanA_used<<<NB_USED, 256>>>();
    scanB_used<<<1, 1024>>>();
    scanC_used<<<NB_USED, 256>>>();

    scanA_hist<<<NB_HIST, 256>>>();
    scanB_hist<<<1, 1024>>>();
    scanC_hist<<<NB_HIST, 256>>>();

    csr_fill<<<cg, 256>>>();

    dim3 gg((NVOX + 127) / 128, KOFF);
    gemm1_kernel<<<gg, 128>>>(feats, W_in);
    route1_kernel<<<(NVOX * 32 + 255) / 256, 256>>>();
    gemm2_kernel<<<gg, 128>>>(W_out);
    route2_kernel<<<(NVOX * 32 + 255) / 256, 256>>>(out);
}